// round 10
// baseline (speedup 1.0000x reference)
#include <cuda_runtime.h>
#include <cstdint>

// Problem constants
#define S    8
#define NCH  7
#define PIX  409600           // 640*640
#define NCHUNK (PIX / 128)    // 3200 warp-chunks of 128 px
#define LAMBDA 0.7f
#define EPSV 1e-6f
#define NBIN 1024             // 10-bit radix digits; key is 30 bits (value in [0,0.5))

// TMA pipeline config
#define TILE_PX  2048
#define NTILES   (PIX / TILE_PX)     // 200
#define NS_LS    4
#define NS_LC    3
#define LS_STAGE_BYTES (TILE_PX * 8)   // pred f32 + label i32       (16 KB)
#define LC_STAGE_BYTES (TILE_PX * 12)  // pred6 + label6 + mask      (24 KB)
#define RD_GRIDX 37                    // 37*8*7 = 2072 blocks
#define RD_BLOCKS (RD_GRIDX * S * 7)
#define RD_SMEM  (128 + NS_LC * LC_STAGE_BYTES)   // 73856 (>= 128 + 4*16K too)
#define HIST_GRIDX 50                  // rare-path hist: 400 blocks, 8192 px each

// ---------------- device scratch (zero at module load; final restores) ------
__device__ uint4    g_wbits[S * NCHUNK];
__device__ int      g_npos[S];
__device__ int      g_nzneg[S];                       // negatives with value > 0
__device__ __align__(16) unsigned g_histA[S][NBIN];
__device__ __align__(16) unsigned g_histB[S][NBIN];
__device__ __align__(16) unsigned g_histC[S][NBIN];
__device__ unsigned g_d0[S], g_krem0[S];
__device__ unsigned g_pref1[S], g_krem1[S];
__device__ float    g_acc[S][21];
__device__ unsigned g_counter;

// Division-free sigmoid: 0.5*tanh(0.5x)+0.5 (single MUFU).
__device__ __forceinline__ float sigmoidf(float x) {
    float t, y = 0.5f * x;
    asm("tanh.approx.f32 %0, %1;" : "=f"(t) : "f"(y));
    return fmaf(0.5f, t, 0.5f);
}

// needs_radix: OHEM active AND the k-th largest negative is strictly > 0.
// If k > nzneg the k-th largest negative is exactly 0.0 -> thr 0 -> M all-ones
// == inactive path. Exact equivalence.
__device__ __forceinline__ bool needs_radix(int s, unsigned& k) {
    int np = g_npos[s];
    k = (unsigned)(np * 3);
    return ((unsigned)(PIX - np) > k) && (k > 0) && (k <= (unsigned)g_nzneg[s]);
}

// ---------------- mbarrier / bulk-async helpers ----------------
__device__ __forceinline__ uint32_t smem_u32(const void* p) {
    return (uint32_t)__cvta_generic_to_shared(p);
}
__device__ __forceinline__ void mbar_init(uint32_t m, uint32_t cnt) {
    asm volatile("mbarrier.init.shared.b64 [%0], %1;" :: "r"(m), "r"(cnt) : "memory");
}
__device__ __forceinline__ void mbar_expect_tx(uint32_t m, uint32_t bytes) {
    asm volatile("mbarrier.arrive.expect_tx.shared.b64 _, [%0], %1;" :: "r"(m), "r"(bytes) : "memory");
}
__device__ __forceinline__ void mbar_wait(uint32_t m, uint32_t parity) {
    asm volatile(
        "{\n\t.reg .pred P;\n\t"
        "WL%=:\n\t"
        "mbarrier.try_wait.parity.acquire.cta.shared::cta.b64 P, [%0], %1, 0x989680;\n\t"
        "@!P bra WL%=;\n\t}"
        :: "r"(m), "r"(parity) : "memory");
}
__device__ __forceinline__ void bulk_g2s(uint32_t dst, const void* src, uint32_t bytes, uint32_t mbar) {
    asm volatile("cp.async.bulk.shared::cluster.global.mbarrier::complete_tx::bytes [%0], [%1], %2, [%3];"
                 :: "r"(dst), "l"(src), "r"(bytes), "r"(mbar) : "memory");
}

// Warp-dedup'd shared histogram add.
__device__ __forceinline__ void hist_add(unsigned* sh, bool participate, unsigned bin) {
    unsigned ballot = __ballot_sync(0xffffffffu, participate);
    if (participate) {
        unsigned grp = __match_any_sync(ballot, bin);
        int leader = __ffs(grp) - 1;
        if ((int)(threadIdx.x & 31) == leader)
            atomicAdd(&sh[bin], (unsigned)__popc(grp));
    }
}

// Radix digit pick over 1024-bin histogram, 256 threads, 2 barriers.
__device__ __forceinline__ void radix_pick(const unsigned* __restrict__ hrow,
                                           unsigned krem, unsigned* shbuf,
                                           unsigned& digit, unsigned& newkrem) {
    int tid = threadIdx.x, lane = tid & 31, w = tid >> 5;
    uint4 h = ((const uint4*)hrow)[tid];
    unsigned local = h.x + h.y + h.z + h.w;
    unsigned v = local;
    #pragma unroll
    for (int o = 1; o < 32; o <<= 1) {
        unsigned u = __shfl_down_sync(0xffffffffu, v, o);
        if (lane + o < 32) v += u;
    }
    if (lane == 0) shbuf[w] = v;
    __syncthreads();
    unsigned after_w = 0;
    #pragma unroll
    for (int j = 0; j < 8; j++) if (j > w) after_w += shbuf[j];
    unsigned suf_me    = v + after_w;
    unsigned suf_after = suf_me - local;
    unsigned s3 = h.w + suf_after;
    unsigned s2 = h.z + s3;
    unsigned s1 = h.y + s2;
    unsigned s0 = h.x + s1;
    if (s0 >= krem && s1 < krem)        { shbuf[8] = 4u*tid + 0u; shbuf[9] = krem - s1; }
    if (s1 >= krem && s2 < krem)        { shbuf[8] = 4u*tid + 1u; shbuf[9] = krem - s2; }
    if (s2 >= krem && s3 < krem)        { shbuf[8] = 4u*tid + 2u; shbuf[9] = krem - s3; }
    if (s3 >= krem && suf_after < krem) { shbuf[8] = 4u*tid + 3u; shbuf[9] = krem - suf_after; }
    __syncthreads();
    digit = shbuf[8]; newkrem = shbuf[9];
}

// ---------------- predn: pure streaming; W bits + npos + nzneg -------------
__global__ void __launch_bounds__(256) k_predn(const float* __restrict__ preds,
                                               const int*   __restrict__ mask) {
    int tid = threadIdx.x, lane = tid & 31;
    int s = blockIdx.y;
    int cpos = 0, cnz = 0;
    #pragma unroll
    for (int it = 0; it < 2; it++) {
        int e = blockIdx.x * 512 + it * 256 + tid;   // float4 index
        int i = e * 4;
        const float4 x = *(const float4*)(preds + (size_t)(s * NCH + 6) * PIX + i);
        const int4   m = *(const int4*)(mask + (size_t)s * PIX + i);
        float pn[4];
        pn[0] = sigmoidf(x.x) * (float)m.x;
        pn[1] = sigmoidf(x.y) * (float)m.y;
        pn[2] = sigmoidf(x.z) * (float)m.z;
        pn[3] = sigmoidf(x.w) * (float)m.w;
        unsigned wb[4];
        #pragma unroll
        for (int j = 0; j < 4; j++) {
            bool ispos = pn[j] >= 0.5f;
            cpos += ispos;
            cnz  += (!ispos) && (pn[j] > 0.f);
            wb[j] = __ballot_sync(0xffffffffu, ispos);
        }
        if (lane == 0)
            g_wbits[s * NCHUNK + (e >> 5)] = make_uint4(wb[0], wb[1], wb[2], wb[3]);
    }
    #pragma unroll
    for (int o = 16; o; o >>= 1) {
        cpos += __shfl_down_sync(0xffffffffu, cpos, o);
        cnz  += __shfl_down_sync(0xffffffffu, cnz, o);
    }
    if (lane == 0) {
        if (cpos) atomicAdd(&g_npos[s], cpos);
        if (cnz)  atomicAdd(&g_nzneg[s], cnz);
    }
}

// ---------------- rare-path radix hists: grid (50, S), 8192 px/block --------
__global__ void k_hist0(const float* __restrict__ preds, const int* __restrict__ mask) {
    int s = blockIdx.y;
    unsigned k;
    if (!needs_radix(s, k)) return;
    __shared__ unsigned sh[NBIN];
    int tid = threadIdx.x;
    ((uint4*)sh)[tid] = make_uint4(0, 0, 0, 0);
    __syncthreads();
    #pragma unroll
    for (int it = 0; it < 8; it++) {
        int i = (blockIdx.x * 2048 + it * 256 + tid) * 4;
        float4 x = *(const float4*)(preds + (size_t)(s * NCH + 6) * PIX + i);
        int4   m = *(const int4*)(mask + (size_t)s * PIX + i);
        float vv[4] = {sigmoidf(x.x) * (float)m.x, sigmoidf(x.y) * (float)m.y,
                       sigmoidf(x.z) * (float)m.z, sigmoidf(x.w) * (float)m.w};
        #pragma unroll
        for (int j = 0; j < 4; j++)
            hist_add(sh, vv[j] < 0.5f, __float_as_uint(vv[j]) >> 20);
    }
    __syncthreads();
    #pragma unroll
    for (int b = tid; b < NBIN; b += 256) {
        unsigned c = sh[b];
        if (c) atomicAdd(&g_histA[s][b], c);
    }
}

__global__ void k_hist1(const float* __restrict__ preds, const int* __restrict__ mask) {
    int s = blockIdx.y;
    unsigned k;
    if (!needs_radix(s, k)) return;
    __shared__ unsigned sh[NBIN];
    __shared__ unsigned shbuf[10];
    int tid = threadIdx.x;
    ((uint4*)sh)[tid] = make_uint4(0, 0, 0, 0);
    unsigned d0, krem0;
    radix_pick(g_histA[s], k, shbuf, d0, krem0);   // barriers also order smem zeroing
    if (blockIdx.x == 0 && tid == 0) { g_d0[s] = d0; g_krem0[s] = krem0; }
    #pragma unroll
    for (int it = 0; it < 8; it++) {
        int i = (blockIdx.x * 2048 + it * 256 + tid) * 4;
        float4 x = *(const float4*)(preds + (size_t)(s * NCH + 6) * PIX + i);
        int4   m = *(const int4*)(mask + (size_t)s * PIX + i);
        float vv[4] = {sigmoidf(x.x) * (float)m.x, sigmoidf(x.y) * (float)m.y,
                       sigmoidf(x.z) * (float)m.z, sigmoidf(x.w) * (float)m.w};
        #pragma unroll
        for (int j = 0; j < 4; j++) {
            unsigned b = __float_as_uint(vv[j]);
            bool hit = (vv[j] < 0.5f) && ((b >> 20) == d0);
            hist_add(sh, hit, (b >> 10) & (NBIN - 1u));
        }
    }
    __syncthreads();
    #pragma unroll
    for (int b = tid; b < NBIN; b += 256) {
        unsigned c = sh[b];
        if (c) atomicAdd(&g_histB[s][b], c);
    }
}

__global__ void k_hist2(const float* __restrict__ preds, const int* __restrict__ mask) {
    int s = blockIdx.y;
    unsigned k;
    if (!needs_radix(s, k)) return;
    __shared__ unsigned sh[NBIN];
    __shared__ unsigned shbuf[10];
    int tid = threadIdx.x;
    ((uint4*)sh)[tid] = make_uint4(0, 0, 0, 0);
    unsigned d1, krem1;
    radix_pick(g_histB[s], g_krem0[s], shbuf, d1, krem1);
    unsigned pref1 = (g_d0[s] << 10) | d1;
    if (blockIdx.x == 0 && tid == 0) { g_pref1[s] = pref1; g_krem1[s] = krem1; }
    #pragma unroll
    for (int it = 0; it < 8; it++) {
        int i = (blockIdx.x * 2048 + it * 256 + tid) * 4;
        float4 x = *(const float4*)(preds + (size_t)(s * NCH + 6) * PIX + i);
        int4   m = *(const int4*)(mask + (size_t)s * PIX + i);
        float vv[4] = {sigmoidf(x.x) * (float)m.x, sigmoidf(x.y) * (float)m.y,
                       sigmoidf(x.z) * (float)m.z, sigmoidf(x.w) * (float)m.w};
        #pragma unroll
        for (int j = 0; j < 4; j++) {
            unsigned b = __float_as_uint(vv[j]);
            bool hit = (vv[j] < 0.5f) && ((b >> 10) == pref1);
            hist_add(sh, hit, b & (NBIN - 1u));
        }
    }
    __syncthreads();
    #pragma unroll
    for (int b = tid; b < NBIN; b += 256) {
        unsigned c = sh[b];
        if (c) atomicAdd(&g_histC[s][b], c);
    }
}

// ---------------- merged reduce: z<6 = Ls channel, z=6 = Lc; + final --------
__global__ void __launch_bounds__(256) k_reduce(const float* __restrict__ preds,
                                                const int* __restrict__ labels,
                                                const int* __restrict__ mask,
                                                float* __restrict__ out) {
    extern __shared__ char dsm[];
    __shared__ unsigned shbuf[10];
    __shared__ float shred[8][3];
    __shared__ bool  is_last;
    uint32_t mbar0 = smem_u32(dsm);
    char* stages = dsm + 128;
    int tid = threadIdx.x, lane = tid & 31, warp = tid >> 5;
    int s = blockIdx.y, c = blockIdx.z;
    int t0 = blockIdx.x;
    float a0 = 0.f, a1 = 0.f, a2 = 0.f;
    int slot_out;

    if (c < 6) {
        // ================= Ls channel c: pred[s,c] + label[s,c] + Wbits =====
        slot_out = 3 + 3 * c;
        const float* pbase = preds + (size_t)(s * NCH + c) * PIX;
        const int*   lbase = labels + (size_t)(s * NCH + c) * PIX;
        const uint4* wbase = g_wbits + s * NCHUNK;

        if (tid == 0) {
            #pragma unroll
            for (int i = 0; i < NS_LS; i++) mbar_init(mbar0 + 8 * i, 1);
            asm volatile("fence.proxy.async.shared::cta;" ::: "memory");
        }
        __syncthreads();
        if (tid == 0) {
            int kk = 0;
            for (int t = t0; t < NTILES && kk < NS_LS; t += RD_GRIDX, kk++) {
                uint32_t sb = smem_u32(stages + kk * LS_STAGE_BYTES);
                mbar_expect_tx(mbar0 + 8 * kk, LS_STAGE_BYTES);
                bulk_g2s(sb, pbase + t * TILE_PX, TILE_PX * 4, mbar0 + 8 * kk);
                bulk_g2s(sb + TILE_PX * 4, lbase + t * TILE_PX, TILE_PX * 4, mbar0 + 8 * kk);
            }
        }
        int cs = 0, cp = 0;   // consumer cursor
        for (int t = t0; t < NTILES; t += RD_GRIDX) {
            mbar_wait(mbar0 + 8 * cs, cp);
            const float4* sp = (const float4*)(stages + cs * LS_STAGE_BYTES);
            const int4*   sl = (const int4*)(stages + cs * LS_STAGE_BYTES + TILE_PX * 4);
            uint4 W4 = wbase[(t * TILE_PX + tid * 8) >> 7];
            unsigned wsh = (unsigned)((tid * 2) & 31);
            #pragma unroll
            for (int r = 0; r < 2; r++) {
                float4 p4 = sp[tid * 2 + r];
                int4   l4 = sl[tid * 2 + r];
                float pv[4] = {p4.x, p4.y, p4.z, p4.w};
                int   lv[4] = {l4.x, l4.y, l4.z, l4.w};
                unsigned wcomp[4] = {W4.x, W4.y, W4.z, W4.w};
                #pragma unroll
                for (int j = 0; j < 4; j++) {
                    float w  = (float)((wcomp[j] >> (wsh + r)) & 1u);
                    float pc = sigmoidf(pv[j]) * w;
                    float lf = (float)lv[j] * w;
                    a0 += pc * lf;
                    a1 += pc * pc;
                    a2 += lf;
                }
            }
            __syncthreads();
            if (tid == 0) {
                int tn = t + RD_GRIDX * NS_LS;
                if (tn < NTILES) {
                    uint32_t sb = smem_u32(stages + cs * LS_STAGE_BYTES);
                    mbar_expect_tx(mbar0 + 8 * cs, LS_STAGE_BYTES);
                    bulk_g2s(sb, pbase + tn * TILE_PX, TILE_PX * 4, mbar0 + 8 * cs);
                    bulk_g2s(sb + TILE_PX * 4, lbase + tn * TILE_PX, TILE_PX * 4, mbar0 + 8 * cs);
                }
            }
            if (++cs == NS_LS) { cs = 0; cp ^= 1; }
        }
    } else {
        // ================= Lc: pred6 + label6 + mask (recompute pn) =========
        slot_out = 0;
        const float* pbase = preds + (size_t)(s * NCH + 6) * PIX;
        const int*   lbase = labels + (size_t)(s * NCH + 6) * PIX;
        const int*   mbase = mask + (size_t)s * PIX;

        unsigned k;
        bool needThr = needs_radix(s, k);
        float thr = 0.f;
        if (needThr) {
            unsigned d2, dummy;
            radix_pick(g_histC[s], g_krem1[s], shbuf, d2, dummy);
            thr = __uint_as_float((g_pref1[s] << 10) | d2);   // exact 30-bit key
        }

        if (tid == 0) {
            #pragma unroll
            for (int i = 0; i < NS_LC; i++) mbar_init(mbar0 + 8 * i, 1);
            asm volatile("fence.proxy.async.shared::cta;" ::: "memory");
        }
        __syncthreads();
        if (tid == 0) {
            int kk = 0;
            for (int t = t0; t < NTILES && kk < NS_LC; t += RD_GRIDX, kk++) {
                uint32_t sb = smem_u32(stages + kk * LC_STAGE_BYTES);
                mbar_expect_tx(mbar0 + 8 * kk, LC_STAGE_BYTES);
                bulk_g2s(sb,               pbase + t * TILE_PX, TILE_PX * 4, mbar0 + 8 * kk);
                bulk_g2s(sb + TILE_PX * 4, lbase + t * TILE_PX, TILE_PX * 4, mbar0 + 8 * kk);
                bulk_g2s(sb + TILE_PX * 8, mbase + t * TILE_PX, TILE_PX * 4, mbar0 + 8 * kk);
            }
        }
        int cs = 0, cp = 0;
        for (int t = t0; t < NTILES; t += RD_GRIDX) {
            mbar_wait(mbar0 + 8 * cs, cp);
            const float4* sp  = (const float4*)(stages + cs * LC_STAGE_BYTES);
            const int4*   sl  = (const int4*)(stages + cs * LC_STAGE_BYTES + TILE_PX * 4);
            const int4*   sm_ = (const int4*)(stages + cs * LC_STAGE_BYTES + TILE_PX * 8);
            #pragma unroll
            for (int r = 0; r < 2; r++) {
                float4 x4 = sp[tid * 2 + r];
                int4   l4 = sl[tid * 2 + r];
                int4   m4 = sm_[tid * 2 + r];
                float xv[4] = {x4.x, x4.y, x4.z, x4.w};
                int   lv[4] = {l4.x, l4.y, l4.z, l4.w};
                int   mv[4] = {m4.x, m4.y, m4.z, m4.w};
                #pragma unroll
                for (int j = 0; j < 4; j++) {
                    float pn = sigmoidf(xv[j]) * (float)mv[j];   // bitwise == predn's
                    float M  = needThr ? (pn >= thr ? 1.f : 0.f) : 1.f;
                    float ln = (float)(lv[j] * mv[j]) * M;
                    float pm = pn * M;
                    a0 += pm * ln;
                    a1 += pm * pn;
                    a2 += ln;
                }
            }
            __syncthreads();
            if (tid == 0) {
                int tn = t + RD_GRIDX * NS_LC;
                if (tn < NTILES) {
                    uint32_t sb = smem_u32(stages + cs * LC_STAGE_BYTES);
                    mbar_expect_tx(mbar0 + 8 * cs, LC_STAGE_BYTES);
                    bulk_g2s(sb,               pbase + tn * TILE_PX, TILE_PX * 4, mbar0 + 8 * cs);
                    bulk_g2s(sb + TILE_PX * 4, lbase + tn * TILE_PX, TILE_PX * 4, mbar0 + 8 * cs);
                    bulk_g2s(sb + TILE_PX * 8, mbase + tn * TILE_PX, TILE_PX * 4, mbar0 + 8 * cs);
                }
            }
            if (++cs == NS_LC) { cs = 0; cp ^= 1; }
        }
    }

    // block reduce 3 accumulators
    #pragma unroll
    for (int o = 16; o; o >>= 1) {
        a0 += __shfl_down_sync(0xffffffffu, a0, o);
        a1 += __shfl_down_sync(0xffffffffu, a1, o);
        a2 += __shfl_down_sync(0xffffffffu, a2, o);
    }
    if (lane == 0) { shred[warp][0] = a0; shred[warp][1] = a1; shred[warp][2] = a2; }
    __syncthreads();
    if (tid < 3) {
        float v = 0.f;
        #pragma unroll
        for (int w = 0; w < 8; w++) v += shred[w][tid];
        atomicAdd(&g_acc[s][slot_out + tid], v);
    }

    __threadfence();
    if (tid == 0)
        is_last = (atomicAdd(&g_counter, 1u) == (unsigned)RD_BLOCKS - 1u);
    __syncthreads();
    if (is_last) {
        for (int b = tid; b < S * NBIN; b += 256) {
            ((unsigned*)g_histA)[b] = 0u;
            ((unsigned*)g_histB)[b] = 0u;
            ((unsigned*)g_histC)[b] = 0u;
        }
        if (tid < S) { g_npos[tid] = 0; g_nzneg[tid] = 0; }
        if (tid == 0) {
            float Lc_s = 0.f, Ls_s = 0.f, loss_s = 0.f;
            for (int ss = 0; ss < S; ss++) {
                float a[21];
                for (int t = 0; t < 21; t++) {
                    a[t] = __ldcg(&g_acc[ss][t]);
                    g_acc[ss][t] = 0.f;
                }
                float Lc = 1.f - (2.f * a[0]) / (a[1] + a[2] + EPSV);
                float d = 0.f;
                for (int cc = 0; cc < 6; cc++)
                    d += (2.f * a[3 + 3 * cc]) / (a[4 + 3 * cc] + a[5 + 3 * cc] + EPSV);
                float Ls = 1.f - d / 6.f;
                Lc_s += Lc; Ls_s += Ls;
                loss_s += LAMBDA * Lc + (1.f - LAMBDA) * Ls;
            }
            out[0] = Lc_s / (float)S;
            out[1] = Ls_s / (float)S;
            out[2] = loss_s / (float)S;
            g_counter = 0u;
        }
    }
}

// ---------------- launch ----------------
extern "C" void kernel_launch(void* const* d_in, const int* in_sizes, int n_in,
                              void* d_out, int out_size) {
    const float* preds  = (const float*)d_in[0];
    const int*   labels = (const int*)d_in[1];
    const int*   mask   = (const int*)d_in[2];
    float* out = (float*)d_out;

    cudaFuncSetAttribute(k_reduce, cudaFuncAttributeMaxDynamicSharedMemorySize, RD_SMEM);

    k_predn<<<dim3(200, S), 256>>>(preds, mask);
    k_hist0<<<dim3(HIST_GRIDX, S), 256>>>(preds, mask);   // no-op on shortcut path
    k_hist1<<<dim3(HIST_GRIDX, S), 256>>>(preds, mask);   // no-op on shortcut path
    k_hist2<<<dim3(HIST_GRIDX, S), 256>>>(preds, mask);   // no-op on shortcut path
    k_reduce<<<dim3(RD_GRIDX, S, 7), 256, RD_SMEM>>>(preds, labels, mask, out);
    (void)in_sizes; (void)n_in; (void)out_size;
}

// round 11
// speedup vs baseline: 2.2589x; 2.2589x over previous
#include <cuda_runtime.h>
#include <cstdint>

// Problem constants
#define S    8
#define NCH  7
#define PIX  409600             // 640*640
#define LAMBDA 0.7f
#define EPSV 1e-6f
#define NBIN 1024               // 10-bit radix digits; key is 30 bits (value in [0,0.5))

// Single-kernel TMA pipeline config
#define TILE_PX   512
#define NTILES    (PIX / TILE_PX)        // 800
#define NSTAGE    3
#define NSTRM     15                     // 7 pred ch + 7 label ch + mask
#define STRIDE_B  (TILE_PX * 4)          // 2048 B per stream
#define STAGE_B   (NSTRM * STRIDE_B)     // 30720 B
#define GRIDX     37
#define NBLK      (GRIDX * S)            // 296 = 148 SMs * 2 blocks
#define SMEM_TOT  (128 + NSTAGE * STAGE_B)   // 92288 B -> 2 blocks/SM

// ---------------- device state (zero at module load; last block restores) ---
__device__ int      g_npos[S];
__device__ int      g_nzneg[S];          // negatives with value > 0
__device__ float    g_acc[S][21];        // [0..2]=Lc(M=1), [3+3c..]=Ls triples
__device__ unsigned g_counter;

// Division-free sigmoid: 0.5*tanh(0.5x)+0.5 (single MUFU).
__device__ __forceinline__ float sigmoidf(float x) {
    float t, y = 0.5f * x;
    asm("tanh.approx.f32 %0, %1;" : "=f"(t) : "f"(y));
    return fmaf(0.5f, t, 0.5f);
}

// ---------------- mbarrier / bulk-async helpers ----------------
__device__ __forceinline__ uint32_t smem_u32(const void* p) {
    return (uint32_t)__cvta_generic_to_shared(p);
}
__device__ __forceinline__ void mbar_init(uint32_t m, uint32_t cnt) {
    asm volatile("mbarrier.init.shared.b64 [%0], %1;" :: "r"(m), "r"(cnt) : "memory");
}
__device__ __forceinline__ void mbar_expect_tx(uint32_t m, uint32_t bytes) {
    asm volatile("mbarrier.arrive.expect_tx.shared.b64 _, [%0], %1;" :: "r"(m), "r"(bytes) : "memory");
}
__device__ __forceinline__ void mbar_wait(uint32_t m, uint32_t parity) {
    asm volatile(
        "{\n\t.reg .pred P;\n\t"
        "WL%=:\n\t"
        "mbarrier.try_wait.parity.acquire.cta.shared::cta.b64 P, [%0], %1, 0x989680;\n\t"
        "@!P bra WL%=;\n\t}"
        :: "r"(m), "r"(parity) : "memory");
}
__device__ __forceinline__ void bulk_g2s(uint32_t dst, const void* src, uint32_t bytes, uint32_t mbar) {
    asm volatile("cp.async.bulk.shared::cluster.global.mbarrier::complete_tx::bytes [%0], [%1], %2, [%3];"
                 :: "r"(dst), "l"(src), "r"(bytes), "r"(mbar) : "memory");
}

// Warp-dedup'd shared histogram add (rare path only).
__device__ __forceinline__ void hist_add(unsigned* sh, bool participate, unsigned bin) {
    unsigned ballot = __ballot_sync(0xffffffffu, participate);
    if (participate) {
        unsigned grp = __match_any_sync(ballot, bin);
        int leader = __ffs(grp) - 1;
        if ((int)(threadIdx.x & 31) == leader)
            atomicAdd(&sh[bin], (unsigned)__popc(grp));
    }
}

// Radix digit pick over 1024-bin shared histogram, 256 threads.
__device__ __forceinline__ void radix_pick(const unsigned* __restrict__ hrow,
                                           unsigned krem, unsigned* shbuf,
                                           unsigned& digit, unsigned& newkrem) {
    int tid = threadIdx.x, lane = tid & 31, w = tid >> 5;
    uint4 h = ((const uint4*)hrow)[tid];
    unsigned local = h.x + h.y + h.z + h.w;
    unsigned v = local;
    #pragma unroll
    for (int o = 1; o < 32; o <<= 1) {
        unsigned u = __shfl_down_sync(0xffffffffu, v, o);
        if (lane + o < 32) v += u;
    }
    if (lane == 0) shbuf[w] = v;
    __syncthreads();
    unsigned after_w = 0;
    #pragma unroll
    for (int j = 0; j < 8; j++) if (j > w) after_w += shbuf[j];
    unsigned suf_me    = v + after_w;
    unsigned suf_after = suf_me - local;
    unsigned s3 = h.w + suf_after;
    unsigned s2 = h.z + s3;
    unsigned s1 = h.y + s2;
    unsigned s0 = h.x + s1;
    if (s0 >= krem && s1 < krem)        { shbuf[8] = 4u*tid + 0u; shbuf[9] = krem - s1; }
    if (s1 >= krem && s2 < krem)        { shbuf[8] = 4u*tid + 1u; shbuf[9] = krem - s2; }
    if (s2 >= krem && s3 < krem)        { shbuf[8] = 4u*tid + 2u; shbuf[9] = krem - s3; }
    if (s3 >= krem && suf_after < krem) { shbuf[8] = 4u*tid + 3u; shbuf[9] = krem - suf_after; }
    __syncthreads();
    digit = shbuf[8]; newkrem = shbuf[9];
}

// ---------------- rare path: exact OHEM threshold + Lc recompute ------------
// Executed by the LAST block only, per sample needing radix. Never taken when
// k > nzneg (k-th largest negative is exactly 0 -> M = all ones). Slow but exact.
__device__ void rare_fix(const float* __restrict__ p6, const int* __restrict__ msk,
                         unsigned k, float* fixv /* shared float[3] */) {
    __shared__ unsigned shbin[NBIN];
    __shared__ unsigned sb2[10];
    __shared__ float red[8][3];
    int tid = threadIdx.x, lane = tid & 31, warp = tid >> 5;

    unsigned pref = 0, krem = k;
    #pragma unroll
    for (int pass = 0; pass < 3; pass++) {
        int shift = 20 - 10 * pass;
        for (int b = tid; b < NBIN; b += 256) shbin[b] = 0u;
        __syncthreads();
        for (int i = tid; i < PIX / 4; i += 256) {
            float4 x = ((const float4*)p6)[i];
            int4   m = ((const int4*)msk)[i];
            float v[4] = {sigmoidf(x.x) * (float)m.x, sigmoidf(x.y) * (float)m.y,
                          sigmoidf(x.z) * (float)m.z, sigmoidf(x.w) * (float)m.w};
            #pragma unroll
            for (int j = 0; j < 4; j++) {
                unsigned b = __float_as_uint(v[j]);
                bool hit = (v[j] < 0.5f) &&
                           (pass == 0 ? true : ((b >> (shift + 10)) == pref));
                hist_add(shbin, hit, (b >> shift) & (NBIN - 1u));
            }
        }
        __syncthreads();
        unsigned d, nk;
        radix_pick(shbin, krem, sb2, d, nk);
        pref = (pass == 0) ? d : ((pref << 10) | d);
        krem = nk;
        __syncthreads();
    }
    float thr = __uint_as_float(pref);

    float a0 = 0.f, a1 = 0.f, a2 = 0.f;
    for (int i = tid; i < PIX / 4; i += 256) {
        float4 x = ((const float4*)p6)[i];
        int4   m = ((const int4*)msk)[i];
        int4   l = ((const int4*)msk)[0];   // placeholder overwritten below
        (void)l;
        float v[4] = {sigmoidf(x.x) * (float)m.x, sigmoidf(x.y) * (float)m.y,
                      sigmoidf(x.z) * (float)m.z, sigmoidf(x.w) * (float)m.w};
        // labels channel 6 pointer is threaded via fixv[3..]; see call site trick:
        const int* l6 = (const int*)__double_as_longlong(0.0);  // unused
        (void)l6;
        // NOTE: label access handled by caller-stored pointer in shared:
        int4 lb = ((const int4*)(((const int**)fixv)[2]))[i];
        int lv[4] = {lb.x, lb.y, lb.z, lb.w};
        int mv[4] = {m.x, m.y, m.z, m.w};
        #pragma unroll
        for (int j = 0; j < 4; j++) {
            float M  = (v[j] >= thr) ? 1.f : 0.f;
            float ln = (float)(lv[j] * mv[j]) * M;
            float pm = v[j] * M;
            a0 += pm * ln;
            a1 += pm * v[j];
            a2 += ln;
        }
    }
    #pragma unroll
    for (int o = 16; o; o >>= 1) {
        a0 += __shfl_down_sync(0xffffffffu, a0, o);
        a1 += __shfl_down_sync(0xffffffffu, a1, o);
        a2 += __shfl_down_sync(0xffffffffu, a2, o);
    }
    if (lane == 0) { red[warp][0] = a0; red[warp][1] = a1; red[warp][2] = a2; }
    __syncthreads();
    if (tid == 0) {
        float r0 = 0.f, r1 = 0.f, r2 = 0.f;
        #pragma unroll
        for (int w = 0; w < 8; w++) { r0 += red[w][0]; r1 += red[w][1]; r2 += red[w][2]; }
        fixv[0] = r0; fixv[1] = r1; fixv[2] = r2;
    }
    __syncthreads();
}

// ---------------- the single fused kernel ----------------
__global__ void __launch_bounds__(256) k_all(const float* __restrict__ preds,
                                             const int* __restrict__ labels,
                                             const int* __restrict__ mask,
                                             float* __restrict__ out) {
    extern __shared__ char dsm[];
    __shared__ float shred[8][21];
    __shared__ bool  is_last;
    __shared__ __align__(16) float fixbuf[8];   // [0..2]=fixed Lc sums, [4..5]=label ptr
    uint32_t mbar0 = smem_u32(dsm);
    char* stages = dsm + 128;
    int tid = threadIdx.x, lane = tid & 31, warp = tid >> 5;
    int s = blockIdx.y;
    int t0 = blockIdx.x;
    const float* pbase = preds + (size_t)s * NCH * PIX;
    const int*   lbase = labels + (size_t)s * NCH * PIX;
    const int*   mbase = mask + (size_t)s * PIX;

    if (tid == 0) {
        #pragma unroll
        for (int i = 0; i < NSTAGE; i++) mbar_init(mbar0 + 8 * i, 1);
        asm volatile("fence.proxy.async.shared::cta;" ::: "memory");
    }
    __syncthreads();

    // prologue: fill all NSTAGE stages (every block has >= 21 tiles)
    if (tid == 0) {
        int kk = 0;
        for (int t = t0; t < NTILES && kk < NSTAGE; t += GRIDX, kk++) {
            uint32_t sb = smem_u32(stages + kk * STAGE_B);
            mbar_expect_tx(mbar0 + 8 * kk, STAGE_B);
            #pragma unroll
            for (int c = 0; c < NCH; c++) {
                bulk_g2s(sb + c * STRIDE_B, pbase + (size_t)c * PIX + t * TILE_PX, STRIDE_B, mbar0 + 8 * kk);
                bulk_g2s(sb + (NCH + c) * STRIDE_B, lbase + (size_t)c * PIX + t * TILE_PX, STRIDE_B, mbar0 + 8 * kk);
            }
            bulk_g2s(sb + 14 * STRIDE_B, mbase + t * TILE_PX, STRIDE_B, mbar0 + 8 * kk);
        }
    }

    float acc[21];
    #pragma unroll
    for (int t = 0; t < 21; t++) acc[t] = 0.f;
    int cpos = 0, cnz = 0;

    int cs = 0, cp = 0;
    for (int t = t0; t < NTILES; t += GRIDX) {
        mbar_wait(mbar0 + 8 * cs, cp);
        const char* st = stages + cs * STAGE_B;
        int2   m2 = ((const int2*)(st + 14 * STRIDE_B))[tid];
        float2 x6 = ((const float2*)(st + 6 * STRIDE_B))[tid];
        int2   l6 = ((const int2*)(st + 13 * STRIDE_B))[tid];
        float pn0 = sigmoidf(x6.x) * (float)m2.x;
        float pn1 = sigmoidf(x6.y) * (float)m2.y;
        bool pos0 = pn0 >= 0.5f, pos1 = pn1 >= 0.5f;
        cpos += pos0 + pos1;
        cnz  += ((!pos0) && (pn0 > 0.f)) + ((!pos1) && (pn1 > 0.f));
        float W0 = pos0 ? 1.f : 0.f, W1 = pos1 ? 1.f : 0.f;
        float ln0 = (float)(l6.x * m2.x), ln1 = (float)(l6.y * m2.y);
        acc[0] += pn0 * ln0 + pn1 * ln1;     // Lc under M=1 hypothesis
        acc[1] += pn0 * pn0 + pn1 * pn1;
        acc[2] += ln0 + ln1;
        #pragma unroll
        for (int c = 0; c < 6; c++) {
            float2 xc = ((const float2*)(st + c * STRIDE_B))[tid];
            int2   lc = ((const int2*)(st + (NCH + c) * STRIDE_B))[tid];
            float pc0 = sigmoidf(xc.x) * W0, pc1 = sigmoidf(xc.y) * W1;
            float lf0 = (float)lc.x * W0,   lf1 = (float)lc.y * W1;
            acc[3 + 3 * c] += pc0 * lf0 + pc1 * lf1;
            acc[4 + 3 * c] += pc0 * pc0 + pc1 * pc1;
            acc[5 + 3 * c] += lf0 + lf1;
        }
        __syncthreads();   // all threads done with slot cs
        if (tid == 0) {
            int tn = t + GRIDX * NSTAGE;
            if (tn < NTILES) {
                uint32_t sb = smem_u32(stages + cs * STAGE_B);
                mbar_expect_tx(mbar0 + 8 * cs, STAGE_B);
                #pragma unroll
                for (int c = 0; c < NCH; c++) {
                    bulk_g2s(sb + c * STRIDE_B, pbase + (size_t)c * PIX + tn * TILE_PX, STRIDE_B, mbar0 + 8 * cs);
                    bulk_g2s(sb + (NCH + c) * STRIDE_B, lbase + (size_t)c * PIX + tn * TILE_PX, STRIDE_B, mbar0 + 8 * cs);
                }
                bulk_g2s(sb + 14 * STRIDE_B, mbase + tn * TILE_PX, STRIDE_B, mbar0 + 8 * cs);
            }
        }
        if (++cs == NSTAGE) { cs = 0; cp ^= 1; }
    }

    // block reduce 21 accumulators + counts
    #pragma unroll
    for (int a = 0; a < 21; a++) {
        float v = acc[a];
        #pragma unroll
        for (int o = 16; o; o >>= 1) v += __shfl_down_sync(0xffffffffu, v, o);
        if (lane == 0) shred[warp][a] = v;
    }
    #pragma unroll
    for (int o = 16; o; o >>= 1) {
        cpos += __shfl_down_sync(0xffffffffu, cpos, o);
        cnz  += __shfl_down_sync(0xffffffffu, cnz, o);
    }
    if (lane == 0) {
        if (cpos) atomicAdd(&g_npos[s], cpos);
        if (cnz)  atomicAdd(&g_nzneg[s], cnz);
    }
    __syncthreads();
    if (tid < 21) {
        float v = 0.f;
        #pragma unroll
        for (int w = 0; w < 8; w++) v += shred[w][tid];
        atomicAdd(&g_acc[s][tid], v);
    }

    // last-block-done: compose + (rare) exact-OHEM fix + state reset
    __threadfence();
    if (tid == 0)
        is_last = (atomicAdd(&g_counter, 1u) == (unsigned)NBLK - 1u);
    __syncthreads();
    if (is_last) {
        float Lc_s = 0.f, Ls_s = 0.f, loss_s = 0.f;   // meaningful on tid 0 only
        for (int ss = 0; ss < S; ss++) {
            int np = __ldcg(&g_npos[ss]);
            int nz = __ldcg(&g_nzneg[ss]);
            unsigned k = (unsigned)(np * 3);
            bool nr = ((unsigned)(PIX - np) > k) && (k > 0) && (k <= (unsigned)nz);
            if (nr) {
                if (tid == 0)
                    ((const int**)fixbuf)[2] = labels + (size_t)(ss * NCH + 6) * PIX;
                __syncthreads();
                rare_fix(preds + (size_t)(ss * NCH + 6) * PIX, mask + (size_t)ss * PIX, k, fixbuf);
            }
            __syncthreads();
            if (tid == 0) {
                float a[21];
                for (int a_i = 0; a_i < 21; a_i++) {
                    a[a_i] = __ldcg(&g_acc[ss][a_i]);
                    g_acc[ss][a_i] = 0.f;
                }
                if (nr) { a[0] = fixbuf[0]; a[1] = fixbuf[1]; a[2] = fixbuf[2]; }
                float Lc = 1.f - (2.f * a[0]) / (a[1] + a[2] + EPSV);
                float d = 0.f;
                for (int cc = 0; cc < 6; cc++)
                    d += (2.f * a[3 + 3 * cc]) / (a[4 + 3 * cc] + a[5 + 3 * cc] + EPSV);
                float Ls = 1.f - d / 6.f;
                Lc_s += Lc; Ls_s += Ls;
                loss_s += LAMBDA * Lc + (1.f - LAMBDA) * Ls;
            }
            __syncthreads();
        }
        if (tid < S) { g_npos[tid] = 0; g_nzneg[tid] = 0; }
        if (tid == 0) {
            out[0] = Lc_s / (float)S;
            out[1] = Ls_s / (float)S;
            out[2] = loss_s / (float)S;
            g_counter = 0u;
        }
    }
}

// ---------------- launch: ONE kernel ----------------
extern "C" void kernel_launch(void* const* d_in, const int* in_sizes, int n_in,
                              void* d_out, int out_size) {
    const float* preds  = (const float*)d_in[0];
    const int*   labels = (const int*)d_in[1];
    const int*   mask   = (const int*)d_in[2];
    float* out = (float*)d_out;

    cudaFuncSetAttribute(k_all, cudaFuncAttributeMaxDynamicSharedMemorySize, SMEM_TOT);
    k_all<<<dim3(GRIDX, S), 256, SMEM_TOT>>>(preds, labels, mask, out);
    (void)in_sizes; (void)n_in; (void)out_size;
}